// round 6
// baseline (speedup 1.0000x reference)
#include <cuda_runtime.h>
#include <cuda_bf16.h>

#define N_PP 8192
#define DIM  16
#define L2E  1.4426950408889634f

#define TPB      256
#define ROWS_PT  256                  // rows staged per pair tile
#define COLS_PT  256                  // cols per tile (1 per thread)
#define NB_T     (N_PP / 256)         // 32 tiles per dim
#define N_PP_ACT 528                  // cb >= rb
#define N_AP_T   (NB_T * NB_T)        // 1024
#define N_EDGE_T 104
#define NITEMS   (N_PP_ACT + N_AP_T + N_EDGE_T)   // 1656
#define GRID     592                  // 148 SMs x 4 CTAs

// accumulators: 0 = nonlink_pp, 1 = link_pp, 2 = nonlink_ap, 3 = link_ap
__device__ double g_acc[4];
__device__ unsigned int g_arrive;
__device__ unsigned int g_next = GRID;

typedef unsigned long long ull;

__device__ __forceinline__ float fast_sqrt(float x) {
    float r; asm("sqrt.approx.f32 %0, %1;" : "=f"(r) : "f"(x)); return r;
}
__device__ __forceinline__ float fast_exp2(float x) {
    float r; asm("ex2.approx.f32 %0, %1;" : "=f"(r) : "f"(x)); return r;
}
__device__ __forceinline__ ull pack2(float lo, float hi) {
    ull r; asm("mov.b64 %0, {%1, %2};" : "=l"(r) : "f"(lo), "f"(hi)); return r;
}
__device__ __forceinline__ void unpack2(ull v, float& lo, float& hi) {
    asm("mov.b64 {%0, %1}, %2;" : "=f"(lo), "=f"(hi) : "l"(v));
}
__device__ __forceinline__ ull fma2(ull a, ull b, ull c) {
    ull d; asm("fma.rn.f32x2 %0, %1, %2, %3;" : "=l"(d) : "l"(a), "l"(b), "l"(c));
    return d;
}

__device__ __forceinline__ float block_reduce(float v, float* sh) {
    #pragma unroll
    for (int off = 16; off > 0; off >>= 1)
        v += __shfl_down_sync(0xffffffffu, v, off);
    int lane = threadIdx.x & 31;
    int w = threadIdx.x >> 5;
    if (lane == 0) sh[w] = v;
    __syncthreads();
    if (w == 0) {
        v = (lane < (int)(TPB >> 5)) ? sh[lane] : 0.f;
        #pragma unroll
        for (int off = 4; off > 0; off >>= 1)
            v += __shfl_down_sync(0xffffffffu, v, off);
    }
    return v;
}

// one column per thread; rows broadcast from smem
template <bool MASKED>
__device__ __forceinline__ float pair_loop(
    const ulonglong2* __restrict__ xs,   // ROWS_PT x 4 (packed -2x)
    const float2* __restrict__ xmeta,    // (xn, lrow*L2E)
    const ull y[8], float yn,
    int row0, int jg)
{
    float accA = 0.f, accB = 0.f;
    #pragma unroll 2
    for (int rr = 0; rr < ROWS_PT; rr++) {
        const ulonglong2* xr = xs + rr * 4;
        ulonglong2 p0 = xr[0], p1 = xr[1], p2 = xr[2], p3 = xr[3];
        float2 m = xmeta[rr];
        ull c = pack2(m.x, yn);
        c = fma2(p0.x, y[0], c);
        c = fma2(p0.y, y[1], c);
        c = fma2(p1.x, y[2], c);
        c = fma2(p1.y, y[3], c);
        c = fma2(p2.x, y[4], c);
        c = fma2(p2.y, y[5], c);
        c = fma2(p3.x, y[6], c);
        c = fma2(p3.y, y[7], c);
        float a0, a1;
        unpack2(c, a0, a1);
        float d2 = a0 + a1;
        float t = fast_exp2(fmaf(fast_sqrt(fmaxf(d2, 0.f)), -L2E, m.y));
        if (MASKED) {
            if (jg <= row0 + rr) t = 0.f;
        }
        if (rr & 1) accB += t; else accA += t;
    }
    return accA + accB;
}

__global__ __launch_bounds__(TPB, 4) void fused_kernel(
    const float* __restrict__ p_star,
    const float* __restrict__ p,
    const float* __restrict__ a,
    const float* __restrict__ beta,
    const float* __restrict__ gamma,
    const int* __restrict__ e_pp,
    const int* __restrict__ e_ap,
    int E,
    float* __restrict__ out)
{
    __shared__ ulonglong2 xs[ROWS_PT * 4];   // 16KB
    __shared__ float2     xmeta[ROWS_PT];    // 2KB
    __shared__ float      red[8];
    __shared__ unsigned   sh_next;

    const int tid = threadIdx.x;
    unsigned item = blockIdx.x;

    while (item < NITEMS) {
        if (item < N_PP_ACT + N_AP_T) {
            // ---------------- pair tile ----------------
            const bool is_pp = (item < N_PP_ACT);
            int rb, cb;
            if (is_pp) {
                int t = (int)item;
                rb = 0;
                #pragma unroll
                for (int r = 0; r < NB_T; r++) {
                    int cnt = NB_T - r;
                    if (t < cnt) { rb = r; break; }
                    t -= cnt;
                }
                cb = rb + t;
            } else {
                int t = (int)item - N_PP_ACT;
                rb = t >> 5;           // /32
                cb = t & 31;
            }
            const int row0 = rb * ROWS_PT;
            const int col0 = cb * COLS_PT;

            // stage row tile (one row per thread)
            {
                int r = row0 + tid;
                const float4* xr = reinterpret_cast<const float4*>(p_star + (size_t)r * DIM);
                float4 v0 = xr[0], v1 = xr[1], v2 = xr[2], v3 = xr[3];
                float xn =
                    v0.x*v0.x + v0.y*v0.y + v0.z*v0.z + v0.w*v0.w +
                    v1.x*v1.x + v1.y*v1.y + v1.z*v1.z + v1.w*v1.w +
                    v2.x*v2.x + v2.y*v2.y + v2.z*v2.z + v2.w*v2.w +
                    v3.x*v3.x + v3.y*v3.y + v3.z*v3.z + v3.w*v3.w;
                ulonglong2* xd = xs + tid * 4;
                xd[0] = make_ulonglong2(pack2(-2.f*v0.x, -2.f*v0.y),
                                        pack2(-2.f*v0.z, -2.f*v0.w));
                xd[1] = make_ulonglong2(pack2(-2.f*v1.x, -2.f*v1.y),
                                        pack2(-2.f*v1.z, -2.f*v1.w));
                xd[2] = make_ulonglong2(pack2(-2.f*v2.x, -2.f*v2.y),
                                        pack2(-2.f*v2.z, -2.f*v2.w));
                xd[3] = make_ulonglong2(pack2(-2.f*v3.x, -2.f*v3.y),
                                        pack2(-2.f*v3.z, -2.f*v3.w));
                float wrow = is_pp ? gamma[r] : beta[r];
                xmeta[tid] = make_float2(xn, wrow * L2E);
            }
            __syncthreads();

            // this thread's column
            const int j = col0 + tid;
            const float* ysrc = is_pp ? p : a;
            ull y[8];
            float yn = 0.f;
            {
                const float4* ya = reinterpret_cast<const float4*>(ysrc + (size_t)j * DIM);
                #pragma unroll
                for (int k = 0; k < 4; k++) {
                    float4 v = ya[k];
                    y[2*k]   = pack2(v.x, v.y);
                    y[2*k+1] = pack2(v.z, v.w);
                    yn += v.x*v.x + v.y*v.y + v.z*v.z + v.w*v.w;
                }
            }

            float acc;
            if (is_pp && cb == rb)
                acc = pair_loop<true >(xs, xmeta, y, yn, row0, j);
            else
                acc = pair_loop<false>(xs, xmeta, y, yn, row0, j);

            const float* wcol = is_pp ? gamma : beta;
            acc *= fast_exp2(wcol[N_PP + j] * L2E);

            float bsum = block_reduce(acc, red);
            if (tid == 0)
                atomicAdd(&g_acc[is_pp ? 0 : 2], (double)bsum);
        } else {
            // ---------------- edge stripe ----------------
            const int eb = (int)item - (N_PP_ACT + N_AP_T);
            float acc_pp = 0.f, acc_ap = 0.f;
            for (int e = eb * TPB + tid; e < E; e += N_EDGE_T * TPB) {
                {
                    int s = e_pp[e];
                    int t = e_pp[E + e];
                    const float4* xsrc = reinterpret_cast<const float4*>(p_star + (size_t)s * DIM);
                    const float4* yt = reinterpret_cast<const float4*>(p + (size_t)t * DIM);
                    float d2 = 0.f;
                    #pragma unroll
                    for (int k = 0; k < 4; k++) {
                        float4 xv = xsrc[k], yv = yt[k];
                        float dx = xv.x - yv.x, dy = xv.y - yv.y;
                        float dz = xv.z - yv.z, dw = xv.w - yv.w;
                        d2 += dx*dx + dy*dy + dz*dz + dw*dw;
                    }
                    acc_pp += gamma[s] + gamma[t + N_PP] - fast_sqrt(d2);
                }
                {
                    int s = e_ap[e];
                    int t = e_ap[E + e];            // in [N_PP, 2*N_PP)
                    const float4* xsrc = reinterpret_cast<const float4*>(p_star + (size_t)s * DIM);
                    const float4* yt = reinterpret_cast<const float4*>(a + (size_t)(t - N_PP) * DIM);
                    float d2 = 0.f;
                    #pragma unroll
                    for (int k = 0; k < 4; k++) {
                        float4 xv = xsrc[k], yv = yt[k];
                        float dx = xv.x - yv.x, dy = xv.y - yv.y;
                        float dz = xv.z - yv.z, dw = xv.w - yv.w;
                        d2 += dx*dx + dy*dy + dz*dz + dw*dw;
                    }
                    acc_ap += beta[s] + beta[t] - fast_sqrt(d2);
                }
            }
            float s_pp = block_reduce(acc_pp, red);
            __syncthreads();
            float s_ap = block_reduce(acc_ap, red);
            if (tid == 0) {
                atomicAdd(&g_acc[1], (double)s_pp);
                atomicAdd(&g_acc[3], (double)s_ap);
            }
        }

        // ---------------- steal next item ----------------
        __syncthreads();
        if (tid == 0) sh_next = atomicAdd(&g_next, 1u);
        __syncthreads();
        item = sh_next;
    }

    // ---------------- arrival + finalize ----------------
    if (tid == 0) {
        __threadfence();
        unsigned old = atomicAdd(&g_arrive, 1u);
        if (old == (unsigned)(gridDim.x - 1)) {
            double nll_pp = -(g_acc[1] - g_acc[0]);
            double nll_ap = -(g_acc[3] - g_acc[2]);
            out[0] = (float)(0.5 * nll_pp / (double)N_PP + 0.5 * nll_ap / (double)N_PP);
            g_acc[0] = 0.0; g_acc[1] = 0.0; g_acc[2] = 0.0; g_acc[3] = 0.0;
            g_arrive = 0u;
            g_next = GRID;
            __threadfence();
        }
    }
}

extern "C" void kernel_launch(void* const* d_in, const int* in_sizes, int n_in,
                              void* d_out, int out_size) {
    const float* p_star = (const float*)d_in[0];
    const float* p      = (const float*)d_in[1];
    const float* a      = (const float*)d_in[2];
    const float* beta   = (const float*)d_in[3];
    const float* gamma  = (const float*)d_in[4];
    const int*   e_pp   = (const int*)d_in[5];
    const int*   e_ap   = (const int*)d_in[6];
    int E = in_sizes[5] / 2;

    fused_kernel<<<GRID, TPB>>>(p_star, p, a, beta, gamma,
                                e_pp, e_ap, E, (float*)d_out);
}

// round 7
// speedup vs baseline: 1.1494x; 1.1494x over previous
#include <cuda_runtime.h>
#include <cuda_bf16.h>

#define N_PP 8192
#define DIM  16
#define L2E  1.4426950408889634f

#define TPB      256
#define ROWS_PT  256                 // rows per pair tile
#define COLS_PT  512                 // cols per pair tile (2/thread)
#define NB_ROW   (N_PP / ROWS_PT)    // 32
#define NB_COL   (N_PP / COLS_PT)    // 16
#define N_PP_ACT 272                 // active pp tiles (cb >= rb/2)
#define N_AP_T   (NB_ROW * NB_COL)   // 512
#define N_EDGE_T 104
#define NB_TOTAL (N_PP_ACT + N_AP_T + N_EDGE_T)   // 888

// accumulators: 0 = nonlink_pp, 1 = link_pp, 2 = nonlink_ap, 3 = link_ap
__device__ double g_acc[4];
__device__ unsigned int g_arrive;

typedef unsigned long long ull;

__device__ __forceinline__ float fast_sqrt(float x) {
    float r; asm("sqrt.approx.f32 %0, %1;" : "=f"(r) : "f"(x)); return r;
}
__device__ __forceinline__ float fast_exp2(float x) {
    float r; asm("ex2.approx.f32 %0, %1;" : "=f"(r) : "f"(x)); return r;
}
__device__ __forceinline__ ull pack2(float lo, float hi) {
    ull r; asm("mov.b64 %0, {%1, %2};" : "=l"(r) : "f"(lo), "f"(hi)); return r;
}
__device__ __forceinline__ void unpack2(ull v, float& lo, float& hi) {
    asm("mov.b64 {%0, %1}, %2;" : "=f"(lo), "=f"(hi) : "l"(v));
}
__device__ __forceinline__ ull fma2(ull a, ull b, ull c) {
    ull d; asm("fma.rn.f32x2 %0, %1, %2, %3;" : "=l"(d) : "l"(a), "l"(b), "l"(c));
    return d;
}

__device__ __forceinline__ float block_reduce(float v, float* sh) {
    #pragma unroll
    for (int off = 16; off > 0; off >>= 1)
        v += __shfl_down_sync(0xffffffffu, v, off);
    int lane = threadIdx.x & 31;
    int w = threadIdx.x >> 5;
    if (lane == 0) sh[w] = v;
    __syncthreads();
    if (w == 0) {
        v = (lane < (int)(TPB >> 5)) ? sh[lane] : 0.f;
        #pragma unroll
        for (int off = 4; off > 0; off >>= 1)
            v += __shfl_down_sync(0xffffffffu, v, off);
    }
    return v;
}

template <bool MASKED>
__device__ __forceinline__ void pair_loop(
    const ulonglong2* __restrict__ xs,   // ROWS_PT x 4 (packed -2x)
    const float2* __restrict__ xmeta,    // (xn, lrow*L2E)
    const ull y0[8], const ull y1[8],
    float yn0, float yn1,
    int row0, int j0g, int j1g,
    float& acc0, float& acc1)
{
    #pragma unroll 2
    for (int rr = 0; rr < ROWS_PT; rr++) {
        const ulonglong2* xr = xs + rr * 4;
        ulonglong2 p0 = xr[0], p1 = xr[1], p2 = xr[2], p3 = xr[3];
        float2 m = xmeta[rr];
        ull c0 = pack2(m.x, yn0);
        ull c1 = pack2(m.x, yn1);
        c0 = fma2(p0.x, y0[0], c0);  c1 = fma2(p0.x, y1[0], c1);
        c0 = fma2(p0.y, y0[1], c0);  c1 = fma2(p0.y, y1[1], c1);
        c0 = fma2(p1.x, y0[2], c0);  c1 = fma2(p1.x, y1[2], c1);
        c0 = fma2(p1.y, y0[3], c0);  c1 = fma2(p1.y, y1[3], c1);
        c0 = fma2(p2.x, y0[4], c0);  c1 = fma2(p2.x, y1[4], c1);
        c0 = fma2(p2.y, y0[5], c0);  c1 = fma2(p2.y, y1[5], c1);
        c0 = fma2(p3.x, y0[6], c0);  c1 = fma2(p3.x, y1[6], c1);
        c0 = fma2(p3.y, y0[7], c0);  c1 = fma2(p3.y, y1[7], c1);
        float a0, a1, b0, b1;
        unpack2(c0, a0, a1); unpack2(c1, b0, b1);
        // |d2|: exact d2 >= 0; rounding may give tiny negative -> fabs folds
        // into the MUFU operand modifier (no extra instruction)
        float d2_0 = fabsf(a0 + a1);
        float d2_1 = fabsf(b0 + b1);
        float t0 = fast_exp2(fmaf(fast_sqrt(d2_0), -L2E, m.y));
        float t1 = fast_exp2(fmaf(fast_sqrt(d2_1), -L2E, m.y));
        if (MASKED) {
            int r = row0 + rr;
            if (j0g <= r) t0 = 0.f;
            if (j1g <= r) t1 = 0.f;
        }
        acc0 += t0;
        acc1 += t1;
    }
}

__global__ __launch_bounds__(TPB, 4) void fused_kernel(
    const float* __restrict__ p_star,
    const float* __restrict__ p,
    const float* __restrict__ a,
    const float* __restrict__ beta,
    const float* __restrict__ gamma,
    const int* __restrict__ e_pp,
    const int* __restrict__ e_ap,
    int E,
    float* __restrict__ out)
{
    __shared__ ulonglong2 xs[ROWS_PT * 4];   // 16KB
    __shared__ float2     xmeta[ROWS_PT];    // 2KB
    __shared__ float      red[8];

    const int bid = blockIdx.x;
    const int tid = threadIdx.x;

    if (bid < N_PP_ACT + N_AP_T) {
        // ---------------- pair tile ----------------
        const bool is_pp = (bid < N_PP_ACT);
        int rb, cb;
        if (is_pp) {
            int t = bid;
            rb = 0;
            #pragma unroll
            for (int r = 0; r < NB_ROW; r++) {
                int cnt = NB_COL - (r >> 1);
                if (t < cnt) { rb = r; break; }
                t -= cnt;
            }
            cb = (rb >> 1) + t;
        } else {
            int t = bid - N_PP_ACT;
            rb = t / NB_COL;
            cb = t % NB_COL;
        }
        const int row0 = rb * ROWS_PT;
        const int col0 = cb * COLS_PT;

        // stage row tile (one row per thread)
        {
            int r = row0 + tid;
            const float4* xr = reinterpret_cast<const float4*>(p_star + (size_t)r * DIM);
            float4 v0 = xr[0], v1 = xr[1], v2 = xr[2], v3 = xr[3];
            float xn =
                v0.x*v0.x + v0.y*v0.y + v0.z*v0.z + v0.w*v0.w +
                v1.x*v1.x + v1.y*v1.y + v1.z*v1.z + v1.w*v1.w +
                v2.x*v2.x + v2.y*v2.y + v2.z*v2.z + v2.w*v2.w +
                v3.x*v3.x + v3.y*v3.y + v3.z*v3.z + v3.w*v3.w;
            ulonglong2* xd = xs + tid * 4;
            xd[0] = make_ulonglong2(pack2(-2.f*v0.x, -2.f*v0.y),
                                    pack2(-2.f*v0.z, -2.f*v0.w));
            xd[1] = make_ulonglong2(pack2(-2.f*v1.x, -2.f*v1.y),
                                    pack2(-2.f*v1.z, -2.f*v1.w));
            xd[2] = make_ulonglong2(pack2(-2.f*v2.x, -2.f*v2.y),
                                    pack2(-2.f*v2.z, -2.f*v2.w));
            xd[3] = make_ulonglong2(pack2(-2.f*v3.x, -2.f*v3.y),
                                    pack2(-2.f*v3.z, -2.f*v3.w));
            float wrow = is_pp ? gamma[r] : beta[r];
            xmeta[tid] = make_float2(xn, wrow * L2E);
        }
        __syncthreads();

        // this thread's two columns
        const int j0 = col0 + 2 * tid;
        const int j1 = j0 + 1;
        const float* ysrc = is_pp ? p : a;
        ull y0[8], y1[8];
        float yn0 = 0.f, yn1 = 0.f;
        {
            const float4* ya = reinterpret_cast<const float4*>(ysrc + (size_t)j0 * DIM);
            #pragma unroll
            for (int k = 0; k < 4; k++) {
                float4 v = ya[k];
                y0[2*k]   = pack2(v.x, v.y);
                y0[2*k+1] = pack2(v.z, v.w);
                yn0 += v.x*v.x + v.y*v.y + v.z*v.z + v.w*v.w;
            }
            const float4* yb = reinterpret_cast<const float4*>(ysrc + (size_t)j1 * DIM);
            #pragma unroll
            for (int k = 0; k < 4; k++) {
                float4 v = yb[k];
                y1[2*k]   = pack2(v.x, v.y);
                y1[2*k+1] = pack2(v.z, v.w);
                yn1 += v.x*v.x + v.y*v.y + v.z*v.z + v.w*v.w;
            }
        }

        float acc0 = 0.f, acc1 = 0.f;
        const bool straddle = is_pp && (col0 < row0 + ROWS_PT);
        if (straddle)
            pair_loop<true >(xs, xmeta, y0, y1, yn0, yn1, row0, j0, j1, acc0, acc1);
        else
            pair_loop<false>(xs, xmeta, y0, y1, yn0, yn1, row0, j0, j1, acc0, acc1);

        const float* wcol = is_pp ? gamma : beta;
        acc0 *= fast_exp2(wcol[N_PP + j0] * L2E);
        acc1 *= fast_exp2(wcol[N_PP + j1] * L2E);

        float bsum = block_reduce(acc0 + acc1, red);
        if (tid == 0)
            atomicAdd(&g_acc[is_pp ? 0 : 2], (double)bsum);
    } else {
        // ---------------- edge stripe ----------------
        const int eb = bid - (N_PP_ACT + N_AP_T);
        float acc_pp = 0.f, acc_ap = 0.f;
        for (int e = eb * TPB + tid; e < E; e += N_EDGE_T * TPB) {
            {
                int s = e_pp[e];
                int t = e_pp[E + e];
                const float4* xsrc = reinterpret_cast<const float4*>(p_star + (size_t)s * DIM);
                const float4* yt = reinterpret_cast<const float4*>(p + (size_t)t * DIM);
                float d2 = 0.f;
                #pragma unroll
                for (int k = 0; k < 4; k++) {
                    float4 xv = xsrc[k], yv = yt[k];
                    float dx = xv.x - yv.x, dy = xv.y - yv.y;
                    float dz = xv.z - yv.z, dw = xv.w - yv.w;
                    d2 += dx*dx + dy*dy + dz*dz + dw*dw;
                }
                acc_pp += gamma[s] + gamma[t + N_PP] - fast_sqrt(d2);
            }
            {
                int s = e_ap[e];
                int t = e_ap[E + e];            // in [N_PP, 2*N_PP)
                const float4* xsrc = reinterpret_cast<const float4*>(p_star + (size_t)s * DIM);
                const float4* yt = reinterpret_cast<const float4*>(a + (size_t)(t - N_PP) * DIM);
                float d2 = 0.f;
                #pragma unroll
                for (int k = 0; k < 4; k++) {
                    float4 xv = xsrc[k], yv = yt[k];
                    float dx = xv.x - yv.x, dy = xv.y - yv.y;
                    float dz = xv.z - yv.z, dw = xv.w - yv.w;
                    d2 += dx*dx + dy*dy + dz*dz + dw*dw;
                }
                acc_ap += beta[s] + beta[t] - fast_sqrt(d2);
            }
        }
        float s_pp = block_reduce(acc_pp, red);
        __syncthreads();
        float s_ap = block_reduce(acc_ap, red);
        if (tid == 0) {
            atomicAdd(&g_acc[1], (double)s_pp);
            atomicAdd(&g_acc[3], (double)s_ap);
        }
    }

    // ---------------- arrival + finalize ----------------
    __syncthreads();
    if (tid == 0) {
        __threadfence();
        unsigned old = atomicAdd(&g_arrive, 1u);
        if (old == (unsigned)(NB_TOTAL - 1)) {
            double nll_pp = -(g_acc[1] - g_acc[0]);
            double nll_ap = -(g_acc[3] - g_acc[2]);
            out[0] = (float)(0.5 * nll_pp / (double)N_PP + 0.5 * nll_ap / (double)N_PP);
            g_acc[0] = 0.0; g_acc[1] = 0.0; g_acc[2] = 0.0; g_acc[3] = 0.0;
            g_arrive = 0u;
            __threadfence();
        }
    }
}

extern "C" void kernel_launch(void* const* d_in, const int* in_sizes, int n_in,
                              void* d_out, int out_size) {
    const float* p_star = (const float*)d_in[0];
    const float* p      = (const float*)d_in[1];
    const float* a      = (const float*)d_in[2];
    const float* beta   = (const float*)d_in[3];
    const float* gamma  = (const float*)d_in[4];
    const int*   e_pp   = (const int*)d_in[5];
    const int*   e_ap   = (const int*)d_in[6];
    int E = in_sizes[5] / 2;

    fused_kernel<<<NB_TOTAL, TPB>>>(p_star, p, a, beta, gamma,
                                    e_pp, e_ap, E, (float*)d_out);
}

// round 8
// speedup vs baseline: 1.2311x; 1.0711x over previous
#include <cuda_runtime.h>
#include <cuda_bf16.h>

#define N_PP 8192
#define DIM  16
#define L2E  1.4426950408889634f

#define TPB      256
#define ROWS_PT  128                 // rows per pair tile (half-height)
#define COLS_PT  512                 // cols per pair tile (2/thread)
#define NB_ROW   (N_PP / ROWS_PT)    // 64
#define NB_COL   (N_PP / COLS_PT)    // 16
#define N_PP_ACT 544                 // active pp tiles
#define N_AP_T   (NB_ROW * NB_COL)   // 1024
#define N_EDGE_T 104
#define NB_TOTAL (N_PP_ACT + N_AP_T + N_EDGE_T)   // 1672

// accumulators: 0 = nonlink_pp, 1 = link_pp, 2 = nonlink_ap, 3 = link_ap
__device__ double g_acc[4];
__device__ unsigned int g_arrive;

typedef unsigned long long ull;

__device__ __forceinline__ float fast_sqrt(float x) {
    float r; asm("sqrt.approx.f32 %0, %1;" : "=f"(r) : "f"(x)); return r;
}
__device__ __forceinline__ float fast_exp2(float x) {
    float r; asm("ex2.approx.f32 %0, %1;" : "=f"(r) : "f"(x)); return r;
}
__device__ __forceinline__ ull pack2(float lo, float hi) {
    ull r; asm("mov.b64 %0, {%1, %2};" : "=l"(r) : "f"(lo), "f"(hi)); return r;
}
__device__ __forceinline__ void unpack2(ull v, float& lo, float& hi) {
    asm("mov.b64 {%0, %1}, %2;" : "=f"(lo), "=f"(hi) : "l"(v));
}
__device__ __forceinline__ ull fma2(ull a, ull b, ull c) {
    ull d; asm("fma.rn.f32x2 %0, %1, %2, %3;" : "=l"(d) : "l"(a), "l"(b), "l"(c));
    return d;
}

__device__ __forceinline__ float block_reduce(float v, float* sh) {
    #pragma unroll
    for (int off = 16; off > 0; off >>= 1)
        v += __shfl_down_sync(0xffffffffu, v, off);
    int lane = threadIdx.x & 31;
    int w = threadIdx.x >> 5;
    if (lane == 0) sh[w] = v;
    __syncthreads();
    if (w == 0) {
        v = (lane < (int)(TPB >> 5)) ? sh[lane] : 0.f;
        #pragma unroll
        for (int off = 4; off > 0; off >>= 1)
            v += __shfl_down_sync(0xffffffffu, v, off);
    }
    return v;
}

template <bool MASKED>
__device__ __forceinline__ void pair_loop(
    const ulonglong2* __restrict__ xs,   // ROWS_PT x 4 (packed -2x)
    const float2* __restrict__ xmeta,    // (xn, lrow*L2E)
    const ull y0[8], const ull y1[8],
    float yn0, float yn1,
    int row0, int j0g, int j1g,
    float& acc0, float& acc1)
{
    #pragma unroll 2
    for (int rr = 0; rr < ROWS_PT; rr++) {
        const ulonglong2* xr = xs + rr * 4;
        ulonglong2 p0 = xr[0], p1 = xr[1], p2 = xr[2], p3 = xr[3];
        float2 m = xmeta[rr];
        ull c0 = pack2(m.x, yn0);
        ull c1 = pack2(m.x, yn1);
        c0 = fma2(p0.x, y0[0], c0);  c1 = fma2(p0.x, y1[0], c1);
        c0 = fma2(p0.y, y0[1], c0);  c1 = fma2(p0.y, y1[1], c1);
        c0 = fma2(p1.x, y0[2], c0);  c1 = fma2(p1.x, y1[2], c1);
        c0 = fma2(p1.y, y0[3], c0);  c1 = fma2(p1.y, y1[3], c1);
        c0 = fma2(p2.x, y0[4], c0);  c1 = fma2(p2.x, y1[4], c1);
        c0 = fma2(p2.y, y0[5], c0);  c1 = fma2(p2.y, y1[5], c1);
        c0 = fma2(p3.x, y0[6], c0);  c1 = fma2(p3.x, y1[6], c1);
        c0 = fma2(p3.y, y0[7], c0);  c1 = fma2(p3.y, y1[7], c1);
        float a0, a1, b0, b1;
        unpack2(c0, a0, a1); unpack2(c1, b0, b1);
        float d2_0 = fabsf(a0 + a1);
        float d2_1 = fabsf(b0 + b1);
        float t0 = fast_exp2(fmaf(fast_sqrt(d2_0), -L2E, m.y));
        float t1 = fast_exp2(fmaf(fast_sqrt(d2_1), -L2E, m.y));
        if (MASKED) {
            int r = row0 + rr;
            if (j0g <= r) t0 = 0.f;
            if (j1g <= r) t1 = 0.f;
        }
        acc0 += t0;
        acc1 += t1;
    }
}

__global__ __launch_bounds__(TPB, 4) void fused_kernel(
    const float* __restrict__ p_star,
    const float* __restrict__ p,
    const float* __restrict__ a,
    const float* __restrict__ beta,
    const float* __restrict__ gamma,
    const int* __restrict__ e_pp,
    const int* __restrict__ e_ap,
    int E,
    float* __restrict__ out)
{
    __shared__ ulonglong2 xs[ROWS_PT * 4];   // 8KB
    __shared__ float2     xmeta[ROWS_PT];    // 1KB
    __shared__ float      red[8];

    const int bid = blockIdx.x;
    const int tid = threadIdx.x;

    if (bid < N_PP_ACT + N_AP_T) {
        // ---------------- pair tile ----------------
        const bool is_pp = (bid < N_PP_ACT);
        int rb, cb;
        if (is_pp) {
            // groups g=rb>>2: rows 4g..4g+3, each with (16-g) tiles, cb in [g,16)
            int t = bid;
            int g = 0;
            #pragma unroll
            for (int i = 0; i < 16; i++) {
                int cnt = 4 * (16 - i);
                if (t < cnt) { g = i; break; }
                t -= cnt;
            }
            int w = 16 - g;
            rb = g * 4 + t / w;
            cb = g + t % w;
        } else {
            int t = bid - N_PP_ACT;
            rb = t >> 4;           // /16
            cb = t & 15;
        }
        const int row0 = rb * ROWS_PT;
        const int col0 = cb * COLS_PT;

        // stage row tile (threads 0..127, one row each)
        if (tid < ROWS_PT) {
            int r = row0 + tid;
            const float4* xr = reinterpret_cast<const float4*>(p_star + (size_t)r * DIM);
            float4 v0 = xr[0], v1 = xr[1], v2 = xr[2], v3 = xr[3];
            float xn =
                v0.x*v0.x + v0.y*v0.y + v0.z*v0.z + v0.w*v0.w +
                v1.x*v1.x + v1.y*v1.y + v1.z*v1.z + v1.w*v1.w +
                v2.x*v2.x + v2.y*v2.y + v2.z*v2.z + v2.w*v2.w +
                v3.x*v3.x + v3.y*v3.y + v3.z*v3.z + v3.w*v3.w;
            ulonglong2* xd = xs + tid * 4;
            xd[0] = make_ulonglong2(pack2(-2.f*v0.x, -2.f*v0.y),
                                    pack2(-2.f*v0.z, -2.f*v0.w));
            xd[1] = make_ulonglong2(pack2(-2.f*v1.x, -2.f*v1.y),
                                    pack2(-2.f*v1.z, -2.f*v1.w));
            xd[2] = make_ulonglong2(pack2(-2.f*v2.x, -2.f*v2.y),
                                    pack2(-2.f*v2.z, -2.f*v2.w));
            xd[3] = make_ulonglong2(pack2(-2.f*v3.x, -2.f*v3.y),
                                    pack2(-2.f*v3.z, -2.f*v3.w));
            float wrow = is_pp ? gamma[r] : beta[r];
            xmeta[tid] = make_float2(xn, wrow * L2E);
        }
        __syncthreads();

        // this thread's two columns
        const int j0 = col0 + 2 * tid;
        const int j1 = j0 + 1;
        const float* ysrc = is_pp ? p : a;
        ull y0[8], y1[8];
        float yn0 = 0.f, yn1 = 0.f;
        {
            const float4* ya = reinterpret_cast<const float4*>(ysrc + (size_t)j0 * DIM);
            #pragma unroll
            for (int k = 0; k < 4; k++) {
                float4 v = ya[k];
                y0[2*k]   = pack2(v.x, v.y);
                y0[2*k+1] = pack2(v.z, v.w);
                yn0 += v.x*v.x + v.y*v.y + v.z*v.z + v.w*v.w;
            }
            const float4* yb = reinterpret_cast<const float4*>(ysrc + (size_t)j1 * DIM);
            #pragma unroll
            for (int k = 0; k < 4; k++) {
                float4 v = yb[k];
                y1[2*k]   = pack2(v.x, v.y);
                y1[2*k+1] = pack2(v.z, v.w);
                yn1 += v.x*v.x + v.y*v.y + v.z*v.z + v.w*v.w;
            }
        }

        float acc0 = 0.f, acc1 = 0.f;
        const bool straddle = is_pp && (col0 < row0 + ROWS_PT);
        if (straddle)
            pair_loop<true >(xs, xmeta, y0, y1, yn0, yn1, row0, j0, j1, acc0, acc1);
        else
            pair_loop<false>(xs, xmeta, y0, y1, yn0, yn1, row0, j0, j1, acc0, acc1);

        const float* wcol = is_pp ? gamma : beta;
        acc0 *= fast_exp2(wcol[N_PP + j0] * L2E);
        acc1 *= fast_exp2(wcol[N_PP + j1] * L2E);

        float bsum = block_reduce(acc0 + acc1, red);
        if (tid == 0)
            atomicAdd(&g_acc[is_pp ? 0 : 2], (double)bsum);
    } else {
        // ---------------- edge stripe ----------------
        const int eb = bid - (N_PP_ACT + N_AP_T);
        float acc_pp = 0.f, acc_ap = 0.f;
        for (int e = eb * TPB + tid; e < E; e += N_EDGE_T * TPB) {
            {
                int s = e_pp[e];
                int t = e_pp[E + e];
                const float4* xsrc = reinterpret_cast<const float4*>(p_star + (size_t)s * DIM);
                const float4* yt = reinterpret_cast<const float4*>(p + (size_t)t * DIM);
                float d2 = 0.f;
                #pragma unroll
                for (int k = 0; k < 4; k++) {
                    float4 xv = xsrc[k], yv = yt[k];
                    float dx = xv.x - yv.x, dy = xv.y - yv.y;
                    float dz = xv.z - yv.z, dw = xv.w - yv.w;
                    d2 += dx*dx + dy*dy + dz*dz + dw*dw;
                }
                acc_pp += gamma[s] + gamma[t + N_PP] - fast_sqrt(d2);
            }
            {
                int s = e_ap[e];
                int t = e_ap[E + e];            // in [N_PP, 2*N_PP)
                const float4* xsrc = reinterpret_cast<const float4*>(p_star + (size_t)s * DIM);
                const float4* yt = reinterpret_cast<const float4*>(a + (size_t)(t - N_PP) * DIM);
                float d2 = 0.f;
                #pragma unroll
                for (int k = 0; k < 4; k++) {
                    float4 xv = xsrc[k], yv = yt[k];
                    float dx = xv.x - yv.x, dy = xv.y - yv.y;
                    float dz = xv.z - yv.z, dw = xv.w - yv.w;
                    d2 += dx*dx + dy*dy + dz*dz + dw*dw;
                }
                acc_ap += beta[s] + beta[t] - fast_sqrt(d2);
            }
        }
        float s_pp = block_reduce(acc_pp, red);
        __syncthreads();
        float s_ap = block_reduce(acc_ap, red);
        if (tid == 0) {
            atomicAdd(&g_acc[1], (double)s_pp);
            atomicAdd(&g_acc[3], (double)s_ap);
        }
    }

    // ---------------- arrival + finalize ----------------
    __syncthreads();
    if (tid == 0) {
        __threadfence();
        unsigned old = atomicAdd(&g_arrive, 1u);
        if (old == (unsigned)(NB_TOTAL - 1)) {
            double nll_pp = -(g_acc[1] - g_acc[0]);
            double nll_ap = -(g_acc[3] - g_acc[2]);
            out[0] = (float)(0.5 * nll_pp / (double)N_PP + 0.5 * nll_ap / (double)N_PP);
            g_acc[0] = 0.0; g_acc[1] = 0.0; g_acc[2] = 0.0; g_acc[3] = 0.0;
            g_arrive = 0u;
            __threadfence();
        }
    }
}

extern "C" void kernel_launch(void* const* d_in, const int* in_sizes, int n_in,
                              void* d_out, int out_size) {
    const float* p_star = (const float*)d_in[0];
    const float* p      = (const float*)d_in[1];
    const float* a      = (const float*)d_in[2];
    const float* beta   = (const float*)d_in[3];
    const float* gamma  = (const float*)d_in[4];
    const int*   e_pp   = (const int*)d_in[5];
    const int*   e_ap   = (const int*)d_in[6];
    int E = in_sizes[5] / 2;

    fused_kernel<<<NB_TOTAL, TPB>>>(p_star, p, a, beta, gamma,
                                    e_pp, e_ap, E, (float*)d_out);
}